// round 6
// baseline (speedup 1.0000x reference)
#include <cuda_runtime.h>
#include <cuda_fp16.h>
#include <mma.h>
#include <cstddef>
#include <cstdint>

using namespace nvcuda;

#define V    6912
#define G4   27648   // 4*V
#define BSZ  16
#define TT   8
#define TR   4
#define BN   128

// ---------------- device scratch (no allocation allowed) ----------------
__device__ __half g_whh16[(size_t)G4 * V];   // fp16 W_hh_enc (written by step-1 GEMM)
__device__ __half g_x16 [128 * V];           // x converted to fp16
__device__ __half g_h16 [BSZ * V];           // encoder h (fp16, GEMM A)
__device__ __half g_hd16[BSZ * TR * V];      // decoder h_d (fp16, GEMM A)
__device__ float  g_h   [BSZ * V];           // encoder h (fp32, fc_enc)
__device__ float  g_c   [BSZ * V];
__device__ float  g_xg  [128 * G4];          // xg accumulator (atomic target)
__device__ float  g_pre [BSZ * G4];          // h@Whh^T accumulator (atomic, L2-resident)
__device__ float  g_dec [BSZ * TR * V];      // fc_dec accumulator (atomic)

__device__ __forceinline__ float sigf(float x) { return 1.0f / (1.0f + expf(-x)); }

__device__ __forceinline__ uint4 pack8(float4 a, float4 b)
{
    __half2 h0 = __floats2half2_rn(a.x, a.y);
    __half2 h1 = __floats2half2_rn(a.z, a.w);
    __half2 h2 = __floats2half2_rn(b.x, b.y);
    __half2 h3 = __floats2half2_rn(b.z, b.w);
    uint4 u;
    u.x = *reinterpret_cast<unsigned*>(&h0);
    u.y = *reinterpret_cast<unsigned*>(&h1);
    u.z = *reinterpret_cast<unsigned*>(&h2);
    u.w = *reinterpret_cast<unsigned*>(&h3);
    return u;
}

// =====================================================================
// fp32 -> fp16 stream converter (x only)
// =====================================================================
__global__ void conv16_kernel(const float* __restrict__ src,
                              __half* __restrict__ dst, int n8)
{
    int idx = blockIdx.x * 256 + threadIdx.x;
    if (idx >= n8) return;
    const float4* s = (const float4*)src + (size_t)idx * 2;
    ((uint4*)dst)[idx] = pack8(s[0], s[1]);
}

// zero-fill (float4 per thread); n4 = count/4
__global__ void zero_kernel(float* __restrict__ dst, int n4)
{
    int idx = blockIdx.x * 256 + threadIdx.x;
    if (idx < n4) ((float4*)dst)[idx] = make_float4(0.f, 0.f, 0.f, 0.f);
}

// =====================================================================
// Register-staged fp16-MMA GEMM with ATOMIC-reduce epilogue.
//   C[m0+m][n] += sum_{k slice} A[m0+m][k] * B[n][k]
//   grid = (N/BN, ksplit, M/BM).   WHALF: B fp16.  WRITEB: store fp16 B.
// =====================================================================
template<int BM, int BK, bool WHALF, bool WRITEB>
__global__ __launch_bounds__(256)
void gemm16(const __half* __restrict__ A, const void* __restrict__ Bv,
            float* __restrict__ C, int N, int klen, __half* __restrict__ Bout)
{
    constexpr int LDS = BK + 8;
    __shared__ __half sA[2][BM][LDS];
    __shared__ __half sB[2][BN][LDS];
    __shared__ float  sC[BM][BN + 4];

    const __half* Bh = (const __half*)Bv;
    const float*  Bf = (const float*)Bv;

    const int tid   = threadIdx.x;
    const int n0    = blockIdx.x * BN;
    const int kbase = blockIdx.y * klen;
    const int m0    = blockIdx.z * BM;
    const int niter = klen / BK;

    constexpr int WARPS_M = (BM <= 16) ? 1 : 2;
    constexpr int WARPS_N = 8 / WARPS_M;
    constexpr int WM = BM / WARPS_M, WN = BN / WARPS_N;
    constexpr int MF = WM / 16, NF = WN / 16;
    const int w  = tid >> 5;
    const int wm = w / WARPS_N, wn = w % WARPS_N;

    wmma::fragment<wmma::accumulator, 16, 16, 16, float> acc[MF][NF];
#pragma unroll
    for (int i = 0; i < MF; i++)
#pragma unroll
        for (int j = 0; j < NF; j++) wmma::fill_fragment(acc[i][j], 0.0f);

    constexpr int CPR   = BK / 8;
    constexpr int BCH   = BN * CPR / 256;
    constexpr int ACH_T = BM * CPR;
    constexpr int ACH   = (ACH_T + 255) / 256;

    uint4 rb[BCH], ra[ACH];

    auto load = [&](int k0) {
#pragma unroll
        for (int p = 0; p < BCH; p++) {
            int c = tid + p * 256;
            int row = c / CPR, kc = (c % CPR) * 8;
            if constexpr (WHALF) {
                rb[p] = *(const uint4*)(Bh + (size_t)(n0 + row) * V + k0 + kc);
            } else {
                const float* s = Bf + (size_t)(n0 + row) * V + k0 + kc;
                rb[p] = pack8(*(const float4*)s, *(const float4*)(s + 4));
                if constexpr (WRITEB)
                    *(uint4*)(Bout + (size_t)(n0 + row) * V + k0 + kc) = rb[p];
            }
        }
#pragma unroll
        for (int p = 0; p < ACH; p++) {
            int c = tid + p * 256;
            if (ACH_T >= (p + 1) * 256 || c < ACH_T) {
                int row = c / CPR, kc = (c % CPR) * 8;
                ra[p] = *(const uint4*)(A + (size_t)(m0 + row) * V + k0 + kc);
            }
        }
    };
    auto store = [&](int buf) {
#pragma unroll
        for (int p = 0; p < BCH; p++) {
            int c = tid + p * 256;
            int row = c / CPR, kc = (c % CPR) * 8;
            *(uint4*)(&sB[buf][row][kc]) = rb[p];
        }
#pragma unroll
        for (int p = 0; p < ACH; p++) {
            int c = tid + p * 256;
            if (ACH_T >= (p + 1) * 256 || c < ACH_T) {
                int row = c / CPR, kc = (c % CPR) * 8;
                *(uint4*)(&sA[buf][row][kc]) = ra[p];
            }
        }
    };

    load(kbase);
    store(0);
    if (niter > 1) load(kbase + BK);
    __syncthreads();

    for (int i = 0; i < niter; i++) {
        int p = i & 1;
        if (i + 1 < niter) store(p ^ 1);
        if (i + 2 < niter) load(kbase + (i + 2) * BK);
#pragma unroll
        for (int kk = 0; kk < BK; kk += 16) {
            wmma::fragment<wmma::matrix_a, 16, 16, 16, __half, wmma::row_major> af[MF];
            wmma::fragment<wmma::matrix_b, 16, 16, 16, __half, wmma::col_major> bf[NF];
#pragma unroll
            for (int i_ = 0; i_ < MF; i_++)
                wmma::load_matrix_sync(af[i_], &sA[p][wm * WM + i_ * 16][kk], LDS);
#pragma unroll
            for (int j_ = 0; j_ < NF; j_++)
                wmma::load_matrix_sync(bf[j_], &sB[p][wn * WN + j_ * 16][kk], LDS);
#pragma unroll
            for (int i_ = 0; i_ < MF; i_++)
#pragma unroll
                for (int j_ = 0; j_ < NF; j_++)
                    wmma::mma_sync(acc[i_][j_], af[i_], bf[j_], acc[i_][j_]);
        }
        __syncthreads();
    }

#pragma unroll
    for (int i_ = 0; i_ < MF; i_++)
#pragma unroll
        for (int j_ = 0; j_ < NF; j_++)
            wmma::store_matrix_sync(&sC[wm * WM + i_ * 16][wn * WN + j_ * 16],
                                    acc[i_][j_], BN + 4, wmma::mem_row_major);
    __syncthreads();
    for (int c = tid; c < BM * BN; c += 256) {
        int m = c / BN, n = c - m * BN;
        atomicAdd(&C[(size_t)(m0 + m) * N + n0 + n], sC[m][n]);
    }
}

// =====================================================================
// cp.async-pipelined fp16 GEMM, BM=16 (recurrence bulk, steps 2..7).
// Atomic-reduce epilogue into C (L2-resident pre buffer).
// =====================================================================
template<int BK, int STAGES>
__global__ __launch_bounds__(256)
void gemm16_ca(const __half* __restrict__ A, const __half* __restrict__ B,
               float* __restrict__ C, int N, int klen)
{
    constexpr int BM  = 16;
    constexpr int LDS = BK + 8;
    __shared__ __half sA[STAGES][BM][LDS];
    __shared__ __half sB[STAGES][BN][LDS];
    __shared__ float  sC[BM][BN + 4];

    const int tid   = threadIdx.x;
    const int n0    = blockIdx.x * BN;
    const int kbase = blockIdx.y * klen;
    const int niter = klen / BK;
    const int w     = tid >> 5;

    wmma::fragment<wmma::accumulator, 16, 16, 16, float> acc;
    wmma::fill_fragment(acc, 0.0f);

    constexpr int CPR   = BK / 8;
    constexpr int BCH   = BN * CPR / 256;
    constexpr int ACH_T = BM * CPR;

    auto stage = [&](int s, int k0) {
#pragma unroll
        for (int p = 0; p < BCH; p++) {
            int c = tid + p * 256;
            int row = c / CPR, kc = (c % CPR) * 8;
            uint32_t d = (uint32_t)__cvta_generic_to_shared(&sB[s][row][kc]);
            const void* g = B + (size_t)(n0 + row) * V + k0 + kc;
            asm volatile("cp.async.cg.shared.global [%0], [%1], 16;\n" :: "r"(d), "l"(g));
        }
        if (tid < ACH_T) {
            int row = tid / CPR, kc = (tid % CPR) * 8;
            uint32_t d = (uint32_t)__cvta_generic_to_shared(&sA[s][row][kc]);
            const void* g = A + (size_t)row * V + k0 + kc;
            asm volatile("cp.async.cg.shared.global [%0], [%1], 16;\n" :: "r"(d), "l"(g));
        }
        asm volatile("cp.async.commit_group;\n");
    };

    int issued = 0;
    for (; issued < STAGES - 1 && issued < niter; issued++)
        stage(issued, kbase + issued * BK);

    for (int i = 0; i < niter; i++) {
        if (issued < niter) { stage(issued % STAGES, kbase + issued * BK); issued++; }
        else                { asm volatile("cp.async.commit_group;\n"); }
        asm volatile("cp.async.wait_group %0;\n" :: "n"(STAGES - 1));
        __syncthreads();
        int s = i % STAGES;
#pragma unroll
        for (int kk = 0; kk < BK; kk += 16) {
            wmma::fragment<wmma::matrix_a, 16, 16, 16, __half, wmma::row_major> af;
            wmma::fragment<wmma::matrix_b, 16, 16, 16, __half, wmma::col_major> bf;
            wmma::load_matrix_sync(af, &sA[s][0][kk], LDS);
            wmma::load_matrix_sync(bf, &sB[s][w * 16][kk], LDS);
            wmma::mma_sync(acc, af, bf, acc);
        }
        __syncthreads();
    }

    wmma::store_matrix_sync(&sC[0][w * 16], acc, BN + 4, wmma::mem_row_major);
    __syncthreads();
    for (int c = tid; c < BM * BN; c += 256) {
        int m = c / BN, n = c - m * BN;
        atomicAdd(&C[(size_t)m * N + n0 + n], sC[m][n]);
    }
}

// =====================================================================
// Encoder step t=0 (h0=c0=0): gates from g_xg + bias; zero g_pre.
// =====================================================================
__global__ void step0_kernel(const float* __restrict__ be)
{
    int idx = blockIdx.x * blockDim.x + threadIdx.x;   // 16*V exactly
    int b = idx / V, j = idx - b * V;
    const float* xg = g_xg + (size_t)(b * 8) * G4;
    float i_ = sigf (xg[j]         + be[j]);
    float gg = tanhf(xg[2 * V + j] + be[2 * V + j]);
    float o_ = sigf (xg[3 * V + j] + be[3 * V + j]);
    float c  = i_ * gg;
    g_c[idx] = c;
    float h  = o_ * tanhf(c);
    g_h[idx]   = h;
    g_h16[idx] = __float2half(h);
    float* pre = g_pre + (size_t)b * G4;   // zero for step-1 atomics
    pre[j] = 0.f; pre[V + j] = 0.f; pre[2 * V + j] = 0.f; pre[3 * V + j] = 0.f;
}

// =====================================================================
// Recurrence pointwise: gates = pre + xg[t] + bias; re-zero pre.
// =====================================================================
__global__ void rec_point_kernel(int t, const float* __restrict__ be)
{
    int idx = blockIdx.x * blockDim.x + threadIdx.x;
    int b = idx / V, j = idx - b * V;
    const float* xg = g_xg + (size_t)(b * 8 + t) * G4;
    float* pre = g_pre + (size_t)b * G4;
    float pi = pre[j]         + xg[j]         + be[j];
    float pf = pre[V + j]     + xg[V + j]     + be[V + j];
    float pg = pre[2 * V + j] + xg[2 * V + j] + be[2 * V + j];
    float po = pre[3 * V + j] + xg[3 * V + j] + be[3 * V + j];
    pre[j] = 0.f; pre[V + j] = 0.f; pre[2 * V + j] = 0.f; pre[3 * V + j] = 0.f;
    float i_ = sigf(pi), f_ = sigf(pf), gg = tanhf(pg), o_ = sigf(po);
    float c  = f_ * g_c[idx] + i_ * gg;
    g_c[idx] = c;
    float h  = o_ * tanhf(c);
    g_h[idx]   = h;
    g_h16[idx] = __float2half(h);
}

// =====================================================================
__global__ void fc_enc_kernel(const float* __restrict__ wgt,
                              const float* __restrict__ bias,
                              float* __restrict__ out)
{
    __shared__ float red[256];
    int b = blockIdx.x;
    const float* h = g_h + (size_t)b * V;
    float s = 0.0f;
    for (int k = threadIdx.x; k < V; k += 256) s = fmaf(h[k], wgt[k], s);
    red[threadIdx.x] = s;
    __syncthreads();
    for (int st = 128; st > 0; st >>= 1) {
        if (threadIdx.x < st) red[threadIdx.x] += red[threadIdx.x + st];
        __syncthreads();
    }
    if (threadIdx.x == 0) out[b] = red[0] + bias[0];
}

// =====================================================================
// Decoder pointwise: gates from pre (single buffer); zero g_dec.
// =====================================================================
__global__ void dec_point_kernel(const float* __restrict__ bd,
                                 const float* __restrict__ Wid,
                                 const float* __restrict__ xrev)
{
    int idx = blockIdx.x * blockDim.x + threadIdx.x;
    int b = idx / V, j = idx - b * V;
    const float* pre = g_pre + (size_t)b * G4;
    float bi = pre[j]         + bd[j];
    float bf = pre[V + j]     + bd[V + j];
    float bg = pre[2 * V + j] + bd[2 * V + j];
    float bo = pre[3 * V + j] + bd[3 * V + j];
    float w0 = Wid[j], w1 = Wid[V + j], w2 = Wid[2 * V + j], w3 = Wid[3 * V + j];
    float ce = g_c[idx];
#pragma unroll
    for (int tr = 0; tr < TR; tr++) {
        float xr = xrev[b * TR + tr];
        float i_ = sigf (bi + xr * w0);
        float f_ = sigf (bf + xr * w1);
        float gg = tanhf(bg + xr * w2);
        float o_ = sigf (bo + xr * w3);
        float cd = f_ * ce + i_ * gg;
        size_t o = (size_t)(b * TR + tr) * V + j;
        g_hd16[o] = __float2half(o_ * tanhf(cd));
        g_dec[o]  = 0.f;                       // zero for fc_dec atomics
    }
}

// =====================================================================
__global__ void dec_out_kernel(const float* __restrict__ fcb,
                               float* __restrict__ out)
{
    int idx = blockIdx.x * blockDim.x + threadIdx.x;   // 64*V exactly
    int m = idx / V, n = idx - m * V;
    float val = g_dec[idx] + fcb[n];
    int b = m >> 2, tr = m & 3;
    size_t base = 16 + (size_t)(b * 12 + tr * 3) * V + n;
    out[base]         = val;
    out[base + V]     = val;
    out[base + 2 * V] = val;
}

// =====================================================================
extern "C" void kernel_launch(void* const* d_in, const int* in_sizes, int n_in,
                              void* d_out, int out_size)
{
    (void)in_sizes; (void)n_in; (void)out_size;
    const float* x        = (const float*)d_in[0];
    const float* x_rev    = (const float*)d_in[1];
    const float* W_ih_enc = (const float*)d_in[2];
    const float* W_hh_enc = (const float*)d_in[3];
    const float* b_enc    = (const float*)d_in[4];
    const float* fc_enc_w = (const float*)d_in[5];
    const float* fc_enc_b = (const float*)d_in[6];
    const float* W_ih_dec = (const float*)d_in[7];
    const float* W_hh_dec = (const float*)d_in[8];
    const float* b_dec    = (const float*)d_in[9];
    const float* fc_dec_w = (const float*)d_in[10];
    const float* fc_dec_b = (const float*)d_in[11];
    float* out = (float*)d_out;

    __half *whh16_p, *x16_p, *h16_p, *hd16_p;
    float  *xg_p, *pre_p, *dec_p;
    cudaGetSymbolAddress((void**)&whh16_p, g_whh16);
    cudaGetSymbolAddress((void**)&x16_p,   g_x16);
    cudaGetSymbolAddress((void**)&h16_p,   g_h16);
    cudaGetSymbolAddress((void**)&hd16_p,  g_hd16);
    cudaGetSymbolAddress((void**)&xg_p,    g_xg);
    cudaGetSymbolAddress((void**)&pre_p,   g_pre);
    cudaGetSymbolAddress((void**)&dec_p,   g_dec);

    // 0) x -> fp16; zero xg accumulator
    conv16_kernel<<<(128 * V / 8 + 255) / 256, 256>>>(x, x16_p, 128 * V / 8);
    zero_kernel<<<(128 * G4 / 4 + 255) / 256, 256>>>(xg_p, 128 * G4 / 4);

    // 1) xg += x @ W_ih_enc^T  (BM=64, ksplit 2, m-blocks 2)
    gemm16<64, 32, false, false><<<dim3(G4 / BN, 2, 2), 256>>>(
        x16_p, W_ih_enc, xg_p, G4, V / 2, nullptr);

    // 2) encoder step 0 (also zeroes pre)
    step0_kernel<<<BSZ * V / 256, 256>>>(b_enc);

    // 3) step 1: GEMM reads fp32 W_hh_enc, converts + writes fp16 copy
    gemm16<16, 64, false, true><<<dim3(G4 / BN, 4, 1), 256>>>(
        h16_p, W_hh_enc, pre_p, G4, V / 4, whh16_p);
    rec_point_kernel<<<BSZ * V / 256, 256>>>(1, b_enc);

    // 4) steps 2..7: cp.async fp16 GEMM, ksplit 8, atomic into pre
    for (int t = 2; t < TT; t++) {
        gemm16_ca<32, 4><<<dim3(G4 / BN, 8), 256>>>(h16_p, whh16_p, pre_p, G4, V / 8);
        rec_point_kernel<<<BSZ * V / 256, 256>>>(t, b_enc);
    }

    // 5) enc_out -> d_out[0..15]
    fc_enc_kernel<<<BSZ, 256>>>(fc_enc_w, fc_enc_b, out);

    // 6) decoder pre += h_enc @ W_hh_dec^T (pre re-zeroed by step-7 rec_point)
    gemm16<16, 64, false, false><<<dim3(G4 / BN, 4, 1), 256>>>(
        h16_p, W_hh_dec, pre_p, G4, V / 4, nullptr);
    dec_point_kernel<<<BSZ * V / 256, 256>>>(b_dec, W_ih_dec, x_rev);

    // 7) dec += h_d @ fc_dec_w^T (BM=64, ksplit 4), then bias + repeat(3)
    gemm16<64, 32, false, false><<<dim3(V / BN, 4, 1), 256>>>(
        hd16_p, fc_dec_w, dec_p, V, V / 4, nullptr);
    dec_out_kernel<<<BSZ * TR * V / 256, 256>>>(fc_dec_b, out);
}